// round 1
// baseline (speedup 1.0000x reference)
#include <cuda_runtime.h>

#define H_DIM 1024
#define NHEAD 16
#define DHEAD 64
#define FPAD 68   // smem row pitch for 64-wide tiles (mult of 4 for float4)

// Scratch (allocation-free rule: __device__ globals). B=2, S=2048, H=1024.
__device__ float g_q[2 * 2048 * 1024];
__device__ float g_k[2 * 2048 * 1024];
__device__ float g_v[2 * 2048 * 1024];
__device__ float g_a[2 * 2048 * 1024];

// ---------------------------------------------------------------------------
// GEMM: C[M,N] = A[M,K] @ W[K,N] + bias[N]   (all row-major, fp32)
// 128x128 block tile, K-step 8, 256 threads, 8x8 per-thread microtile.
// ---------------------------------------------------------------------------
__global__ __launch_bounds__(256) void gemm_bias_kernel(
    const float* __restrict__ A, const float* __restrict__ W,
    const float* __restrict__ bias, float* __restrict__ C,
    int M, int N, int K)
{
    __shared__ float As[8 * 132];   // [k][row], padded pitch 132
    __shared__ float Ws[8 * 132];   // [k][col]

    const int tid  = threadIdx.x;
    const int brow = blockIdx.y * 128;
    const int bcol = blockIdx.x * 128;
    const int tr   = (tid >> 4) * 8;   // row within tile
    const int tc   = (tid & 15) * 8;   // col within tile

    float acc[8][8];
#pragma unroll
    for (int i = 0; i < 8; i++)
#pragma unroll
        for (int j = 0; j < 8; j++) acc[i][j] = 0.0f;

    const float* Aptr = A + (long)(brow + (tid >> 1)) * K + ((tid & 1) << 2);
    const float* Wptr = W + (long)(tid >> 5) * N + bcol + ((tid & 31) << 2);

    for (int k0 = 0; k0 < K; k0 += 8) {
        float4 a4 = *(const float4*)(Aptr + k0);
        float4 w4 = *(const float4*)(Wptr + (long)k0 * N);

        const int ar = tid >> 1;
        const int ac = (tid & 1) << 2;
        As[(ac + 0) * 132 + ar] = a4.x;
        As[(ac + 1) * 132 + ar] = a4.y;
        As[(ac + 2) * 132 + ar] = a4.z;
        As[(ac + 3) * 132 + ar] = a4.w;
        *(float4*)&Ws[(tid >> 5) * 132 + ((tid & 31) << 2)] = w4;
        __syncthreads();

#pragma unroll
        for (int kk = 0; kk < 8; kk++) {
            float a[8], b[8];
            *(float4*)&a[0] = *(const float4*)&As[kk * 132 + tr];
            *(float4*)&a[4] = *(const float4*)&As[kk * 132 + tr + 4];
            *(float4*)&b[0] = *(const float4*)&Ws[kk * 132 + tc];
            *(float4*)&b[4] = *(const float4*)&Ws[kk * 132 + tc + 4];
#pragma unroll
            for (int i = 0; i < 8; i++)
#pragma unroll
                for (int j = 0; j < 8; j++)
                    acc[i][j] = fmaf(a[i], b[j], acc[i][j]);
        }
        __syncthreads();
    }

    float brg[8];
#pragma unroll
    for (int j = 0; j < 8; j++) brg[j] = bias[bcol + tc + j];

#pragma unroll
    for (int i = 0; i < 8; i++) {
        float* crow = C + (long)(brow + tr + i) * N + bcol + tc;
#pragma unroll
        for (int j = 0; j < 8; j += 4) {
            float4 o;
            o.x = acc[i][j + 0] + brg[j + 0];
            o.y = acc[i][j + 1] + brg[j + 1];
            o.z = acc[i][j + 2] + brg[j + 2];
            o.w = acc[i][j + 3] + brg[j + 3];
            *(float4*)&crow[j] = o;
        }
    }
}

// ---------------------------------------------------------------------------
// Flash attention: one CTA = 64 Q rows of one (b, h).
// Online softmax; K/V tiles of 64 rows streamed through smem.
// 256 threads in 16x16 layout, each owns 4x4 of the 64x64 score tile
// and 4 rows x 4 d-cols of the output accumulator.
// ---------------------------------------------------------------------------
__global__ __launch_bounds__(256) void flash_attn_kernel(
    const float* __restrict__ Q, const float* __restrict__ K,
    const float* __restrict__ V, const int* __restrict__ mask,
    float* __restrict__ O, int S)
{
    extern __shared__ float sm[];
    float* Qst = sm;                  // [d=64][row] pitch FPAD (transposed)
    float* Kst = Qst + 64 * FPAD;     // [d=64][row] (transposed)
    float* Vs  = Kst + 64 * FPAD;     // [row][d]
    float* Ps  = Vs  + 64 * FPAD;     // [qrow][krow]

    const int tid = threadIdx.x;
    const int qt = blockIdx.x, h = blockIdx.y, b = blockIdx.z;
    const int tr = (tid >> 4) * 4;    // q-rows owned
    const int tc = (tid & 15) * 4;    // cols owned (score-k or d)

    const float* Qb = Q + ((long)(b * S + qt * 64)) * H_DIM + h * DHEAD;
    const float* Kb = K + ((long)b * S) * H_DIM + h * DHEAD;
    const float* Vb = V + ((long)b * S) * H_DIM + h * DHEAD;
    const int*   Mb = mask + (long)b * S * S + (long)(qt * 64) * S;

    // Load Q tile transposed: Qst[d][r]
    for (int i = tid; i < 64 * 16; i += 256) {
        int r = i >> 4, c = (i & 15) << 2;
        float4 v = *(const float4*)(Qb + (long)r * H_DIM + c);
        Qst[(c + 0) * FPAD + r] = v.x;
        Qst[(c + 1) * FPAD + r] = v.y;
        Qst[(c + 2) * FPAD + r] = v.z;
        Qst[(c + 3) * FPAD + r] = v.w;
    }

    float m_i[4], l_i[4], acc[4][4];
#pragma unroll
    for (int i = 0; i < 4; i++) {
        m_i[i] = -1e30f;
        l_i[i] = 0.0f;
#pragma unroll
        for (int j = 0; j < 4; j++) acc[i][j] = 0.0f;
    }

    const float scale = 0.125f;  // 1/sqrt(64)
    const int ntiles = S / 64;

    for (int kt = 0; kt < ntiles; kt++) {
        __syncthreads();  // protect Kst/Vs/Ps reuse (and Qst fill on iter 0)
        const float* Kp = Kb + (long)(kt * 64) * H_DIM;
        const float* Vp = Vb + (long)(kt * 64) * H_DIM;
        for (int i = tid; i < 64 * 16; i += 256) {
            int r = i >> 4, c = (i & 15) << 2;
            float4 kv = *(const float4*)(Kp + (long)r * H_DIM + c);
            Kst[(c + 0) * FPAD + r] = kv.x;
            Kst[(c + 1) * FPAD + r] = kv.y;
            Kst[(c + 2) * FPAD + r] = kv.z;
            Kst[(c + 3) * FPAD + r] = kv.w;
            float4 vv = *(const float4*)(Vp + (long)r * H_DIM + c);
            *(float4*)&Vs[r * FPAD + c] = vv;
        }
        __syncthreads();

        // s = Q @ K^T over d=64
        float s[4][4];
#pragma unroll
        for (int i = 0; i < 4; i++)
#pragma unroll
            for (int j = 0; j < 4; j++) s[i][j] = 0.0f;

#pragma unroll 8
        for (int d = 0; d < 64; d++) {
            float4 a = *(const float4*)&Qst[d * FPAD + tr];
            float4 bb = *(const float4*)&Kst[d * FPAD + tc];
            float av[4] = {a.x, a.y, a.z, a.w};
            float bv[4] = {bb.x, bb.y, bb.z, bb.w};
#pragma unroll
            for (int i = 0; i < 4; i++)
#pragma unroll
                for (int j = 0; j < 4; j++)
                    s[i][j] = fmaf(av[i], bv[j], s[i][j]);
        }

        // scale + mask
#pragma unroll
        for (int i = 0; i < 4; i++) {
            int4 mm = *(const int4*)&Mb[(long)(tr + i) * S + kt * 64 + tc];
            s[i][0] = (mm.x == 0) ? -10000.0f : s[i][0] * scale;
            s[i][1] = (mm.y == 0) ? -10000.0f : s[i][1] * scale;
            s[i][2] = (mm.z == 0) ? -10000.0f : s[i][2] * scale;
            s[i][3] = (mm.w == 0) ? -10000.0f : s[i][3] * scale;
        }

        // online softmax update (row reduction across the 16 tx lanes)
#pragma unroll
        for (int i = 0; i < 4; i++) {
            float rm = fmaxf(fmaxf(s[i][0], s[i][1]), fmaxf(s[i][2], s[i][3]));
#pragma unroll
            for (int off = 8; off >= 1; off >>= 1)
                rm = fmaxf(rm, __shfl_xor_sync(0xffffffffu, rm, off));
            float mnew = fmaxf(m_i[i], rm);
            float corr = __expf(m_i[i] - mnew);
            float rs = 0.0f;
#pragma unroll
            for (int j = 0; j < 4; j++) {
                float p = __expf(s[i][j] - mnew);
                s[i][j] = p;
                rs += p;
            }
#pragma unroll
            for (int off = 8; off >= 1; off >>= 1)
                rs += __shfl_xor_sync(0xffffffffu, rs, off);
            l_i[i] = l_i[i] * corr + rs;
            m_i[i] = mnew;
#pragma unroll
            for (int j = 0; j < 4; j++) acc[i][j] *= corr;
        }

        // store P, then O += P @ V
#pragma unroll
        for (int i = 0; i < 4; i++) {
            float4 p4 = make_float4(s[i][0], s[i][1], s[i][2], s[i][3]);
            *(float4*)&Ps[(tr + i) * FPAD + tc] = p4;
        }
        __syncthreads();

#pragma unroll 8
        for (int k = 0; k < 64; k++) {
            float p0 = Ps[(tr + 0) * FPAD + k];
            float p1 = Ps[(tr + 1) * FPAD + k];
            float p2 = Ps[(tr + 2) * FPAD + k];
            float p3 = Ps[(tr + 3) * FPAD + k];
            float4 vv = *(const float4*)&Vs[k * FPAD + tc];
            float vrow[4] = {vv.x, vv.y, vv.z, vv.w};
            float pr[4] = {p0, p1, p2, p3};
#pragma unroll
            for (int i = 0; i < 4; i++)
#pragma unroll
                for (int j = 0; j < 4; j++)
                    acc[i][j] = fmaf(pr[i], vrow[j], acc[i][j]);
        }
    }

    // epilogue: divide by l, write to [B,S,H] layout at this head's columns
    float* Ob = O + ((long)(b * S + qt * 64)) * H_DIM + h * DHEAD;
#pragma unroll
    for (int i = 0; i < 4; i++) {
        float inv = 1.0f / l_i[i];
        float4 o = make_float4(acc[i][0] * inv, acc[i][1] * inv,
                               acc[i][2] * inv, acc[i][3] * inv);
        *(float4*)&Ob[(long)(tr + i) * H_DIM + tc] = o;
    }
}

// ---------------------------------------------------------------------------
// Launch
// ---------------------------------------------------------------------------
extern "C" void kernel_launch(void* const* d_in, const int* in_sizes, int n_in,
                              void* d_out, int out_size)
{
    const float* q   = (const float*)d_in[0];
    const float* k   = (const float*)d_in[1];
    const float* v   = (const float*)d_in[2];
    const int*   msk = (const int*)d_in[3];
    const float* w_q = (const float*)d_in[4];
    const float* b_q = (const float*)d_in[5];
    const float* w_k = (const float*)d_in[6];
    const float* b_k = (const float*)d_in[7];
    const float* w_v = (const float*)d_in[8];
    const float* b_v = (const float*)d_in[9];
    const float* w_o = (const float*)d_in[10];
    const float* b_o = (const float*)d_in[11];
    float* out = (float*)d_out;

    // Derive shapes: in_sizes[0] = B*S*H, in_sizes[3] = B*S*S
    const int BS = in_sizes[0] / H_DIM;       // B*S
    const int S  = in_sizes[3] / BS;
    const int B  = BS / S;

    float *gq, *gk, *gv, *ga;
    cudaGetSymbolAddress((void**)&gq, g_q);
    cudaGetSymbolAddress((void**)&gk, g_k);
    cudaGetSymbolAddress((void**)&gv, g_v);
    cudaGetSymbolAddress((void**)&ga, g_a);

    const int M = BS, N = H_DIM, K = H_DIM;
    dim3 gb(N / 128, M / 128);

    gemm_bias_kernel<<<gb, 256>>>(q, w_q, b_q, gq, M, N, K);
    gemm_bias_kernel<<<gb, 256>>>(k, w_k, b_k, gk, M, N, K);
    gemm_bias_kernel<<<gb, 256>>>(v, w_v, b_v, gv, M, N, K);

    const size_t SMEM = (size_t)4 * 64 * FPAD * sizeof(float);  // 69632 B
    cudaFuncSetAttribute(flash_attn_kernel,
                         cudaFuncAttributeMaxDynamicSharedMemorySize, (int)SMEM);
    flash_attn_kernel<<<dim3(S / 64, NHEAD, B), 256, SMEM>>>(gq, gk, gv, msk, ga, S);

    gemm_bias_kernel<<<gb, 256>>>(ga, w_o, b_o, out, M, N, K);
}

// round 3
// speedup vs baseline: 1.3784x; 1.3784x over previous
#include <cuda_runtime.h>
#include <cuda_bf16.h>
#include <cstdint>

#define H_DIM 1024
#define NHEAD 16
#define DHEAD 64
#define FPAD 68

// ---------------- scratch (__device__ globals; no allocs allowed) ----------
__device__ float g_q[2 * 2048 * 1024];
__device__ float g_k[2 * 2048 * 1024];
__device__ float g_v[2 * 2048 * 1024];
__device__ float g_a[2 * 2048 * 1024];
__device__ __nv_bfloat16 g_ah[2 * 2048 * 1024];
__device__ __nv_bfloat16 g_al[2 * 2048 * 1024];
__device__ __nv_bfloat16 g_wh[1024 * 1024];
__device__ __nv_bfloat16 g_wl[1024 * 1024];

// ---------------- helpers --------------------------------------------------
__device__ __forceinline__ uint32_t smem_u32(const void* p) {
    uint32_t a;
    asm("{ .reg .u64 t; cvta.to.shared.u64 t, %1; cvt.u32.u64 %0, t; }" : "=r"(a) : "l"(p));
    return a;
}
__device__ __forceinline__ uint32_t swz(uint32_t off) {
    return off ^ ((off >> 3) & 0x70);
}
__device__ __forceinline__ void cp_async16(uint32_t saddr, const void* g) {
    asm volatile("cp.async.cg.shared.global [%0], [%1], 16;" :: "r"(saddr), "l"(g));
}
__device__ __forceinline__ void cp_commit() {
    asm volatile("cp.async.commit_group;" ::: "memory");
}
template <int N>
__device__ __forceinline__ void cp_wait() {
    asm volatile("cp.async.wait_group %0;" :: "n"(N) : "memory");
}
__device__ __forceinline__ void ldsm4(uint32_t* r, uint32_t addr) {
    asm volatile("ldmatrix.sync.aligned.m8n8.x4.shared.b16 {%0,%1,%2,%3}, [%4];"
                 : "=r"(r[0]), "=r"(r[1]), "=r"(r[2]), "=r"(r[3]) : "r"(addr));
}
__device__ __forceinline__ uint32_t lds32(uint32_t addr) {
    uint32_t v;
    asm volatile("ld.shared.b32 %0, [%1];" : "=r"(v) : "r"(addr));
    return v;
}
__device__ __forceinline__ void mma16816(float* c, const uint32_t* a, const uint32_t* b) {
    asm volatile(
        "mma.sync.aligned.m16n8k16.row.col.f32.bf16.bf16.f32 "
        "{%0,%1,%2,%3}, {%4,%5,%6,%7}, {%8,%9}, {%0,%1,%2,%3};"
        : "+f"(c[0]), "+f"(c[1]), "+f"(c[2]), "+f"(c[3])
        : "r"(a[0]), "r"(a[1]), "r"(a[2]), "r"(a[3]), "r"(b[0]), "r"(b[1]));
}

// ---------------- precision-split conversion kernels -----------------------
__global__ __launch_bounds__(256) void aconv_kernel(
    const float* __restrict__ A, __nv_bfloat16* __restrict__ Ah,
    __nv_bfloat16* __restrict__ Al, int n)
{
    int i = (blockIdx.x * 256 + threadIdx.x) * 4;
    if (i >= n) return;
    float4 v = *(const float4*)(A + i);
    float f[4] = {v.x, v.y, v.z, v.w};
    __nv_bfloat16 h[4], l[4];
#pragma unroll
    for (int j = 0; j < 4; j++) {
        h[j] = __float2bfloat16(f[j]);
        l[j] = __float2bfloat16(f[j] - __bfloat162float(h[j]));
    }
    *(__nv_bfloat162*)(Ah + i)     = __nv_bfloat162(h[0], h[1]);
    *(__nv_bfloat162*)(Ah + i + 2) = __nv_bfloat162(h[2], h[3]);
    *(__nv_bfloat162*)(Al + i)     = __nv_bfloat162(l[0], l[1]);
    *(__nv_bfloat162*)(Al + i + 2) = __nv_bfloat162(l[2], l[3]);
}

// transpose W [K,N] -> Wt [N,K] with hi/lo split
__global__ __launch_bounds__(256) void wconv_kernel(
    const float* __restrict__ W, __nv_bfloat16* __restrict__ Wh,
    __nv_bfloat16* __restrict__ Wl)
{
    __shared__ float t[32][33];
    int bx = blockIdx.x * 32, by = blockIdx.y * 32;
    int tx = threadIdx.x, ty = threadIdx.y;
#pragma unroll
    for (int j = 0; j < 32; j += 8)
        t[ty + j][tx] = W[(size_t)(by + ty + j) * H_DIM + bx + tx];
    __syncthreads();
#pragma unroll
    for (int j = 0; j < 32; j += 8) {
        float v = t[tx][ty + j];
        __nv_bfloat16 h = __float2bfloat16(v);
        __nv_bfloat16 l = __float2bfloat16(v - __bfloat162float(h));
        size_t o = (size_t)(bx + ty + j) * H_DIM + by + tx;
        Wh[o] = h;
        Wl[o] = l;
    }
}

// ---------------- HMMA GEMM: C = A @ Wt^T + bias ---------------------------
// A: [M,1024] bf16 hi/lo; Wt: [1024,1024] bf16 hi/lo (pre-transposed [N,K]).
// CTA 128x128, 8 warps (2x4), warp tile 64x32, BK=64, cp.async double buffer.
// 3-term split: C = Ah*Bh + Al*Bh + Ah*Bl (fp32 accum).
#define GK 1024
#define TILE16K 16384              /* one 128x64 bf16 tile */
#define STAGEB  (4 * TILE16K)      /* Ah Al Bh Bl = 64 KB   */
#define NSTG 16                    /* K / 64                */
#define GEMM_SMEM (2 * STAGEB)

__global__ __launch_bounds__(256) void hmma_gemm_kernel(
    const __nv_bfloat16* __restrict__ Ah, const __nv_bfloat16* __restrict__ Al,
    const __nv_bfloat16* __restrict__ Bh, const __nv_bfloat16* __restrict__ Bl,
    const float* __restrict__ bias, float* __restrict__ C, int N)
{
    extern __shared__ char smem[];
    const uint32_t sb = smem_u32(smem);
    const int tid = threadIdx.x;
    const int wid = tid >> 5, lane = tid & 31;
    const int warp_m = wid & 1, warp_n = wid >> 1;
    const int brow = blockIdx.y * 128, bcol = blockIdx.x * 128;

    const __nv_bfloat16* srcs[4] = {
        Ah + (size_t)brow * GK, Al + (size_t)brow * GK,
        Bh + (size_t)bcol * GK, Bl + (size_t)bcol * GK };

    // per-thread fill assignment: 4 chunks (of 1024) per tile
    const int frow[4] = { (tid + 0) >> 3, (tid + 256) >> 3,
                          (tid + 512) >> 3, (tid + 768) >> 3 };
    const int fchk[4] = { (tid + 0) & 7, (tid + 256) & 7,
                          (tid + 512) & 7, (tid + 768) & 7 };

    // fill stage `buf` with K-chunk starting at k0
    auto fill = [&](int buf, int k0) {
        const uint32_t stb = sb + buf * STAGEB;
#pragma unroll
        for (int t = 0; t < 4; t++) {
            const __nv_bfloat16* p = srcs[t] + k0;
#pragma unroll
            for (int i = 0; i < 4; i++) {
                const __nv_bfloat16* g = p + (size_t)frow[i] * GK + fchk[i] * 8;
                cp_async16(stb + t * TILE16K + swz(frow[i] * 128 + fchk[i] * 16), g);
            }
        }
        cp_commit();
    };

    float c[4][4][4];
#pragma unroll
    for (int i = 0; i < 4; i++)
#pragma unroll
        for (int j = 0; j < 4; j++)
#pragma unroll
            for (int e = 0; e < 4; e++) c[i][j][e] = 0.0f;

    // A ldmatrix per-thread geometry
    const int a_row = warp_m * 64 + (lane & 15);   // + fm*16
    const int a_chk = lane >> 4;                   // + 2*k16
    // B LDS geometry
    const int b_n  = warp_n * 32 + (lane >> 2);    // + fn*8
    const int b_kb = 4 * (lane & 3);               // byte offset of k-pair

    fill(0, 0);

    for (int s = 0; s < NSTG; s++) {
        if (s + 1 < NSTG) fill((s + 1) & 1, (s + 1) * 64);
        if (s + 1 < NSTG) cp_wait<1>(); else cp_wait<0>();
        __syncthreads();

        const uint32_t stb = sb + (s & 1) * STAGEB;
        const uint32_t ah_b = stb, al_b = stb + TILE16K;
        const uint32_t bh_b = stb + 2 * TILE16K, bl_b = stb + 3 * TILE16K;

#pragma unroll
        for (int k16 = 0; k16 < 4; k16++) {
            uint32_t ah[4][4], al[4][4], bh[4][2], bl[4][2];
#pragma unroll
            for (int fm = 0; fm < 4; fm++) {
                uint32_t off = swz((uint32_t)((a_row + fm * 16) * 128 + (a_chk + 2 * k16) * 16));
                ldsm4(ah[fm], ah_b + off);
                ldsm4(al[fm], al_b + off);
            }
#pragma unroll
            for (int fn = 0; fn < 4; fn++) {
                uint32_t o0 = (uint32_t)((b_n + fn * 8) * 128 + k16 * 32 + b_kb);
                uint32_t s0 = swz(o0), s1 = swz(o0 + 16);
                bh[fn][0] = lds32(bh_b + s0);
                bh[fn][1] = lds32(bh_b + s1);
                bl[fn][0] = lds32(bl_b + s0);
                bl[fn][1] = lds32(bl_b + s1);
            }
#pragma unroll
            for (int fm = 0; fm < 4; fm++)
#pragma unroll
                for (int fn = 0; fn < 4; fn++) {
                    mma16816(c[fm][fn], ah[fm], bh[fn]);
                    mma16816(c[fm][fn], al[fm], bh[fn]);
                    mma16816(c[fm][fn], ah[fm], bl[fn]);
                }
        }
        __syncthreads();
    }

    // epilogue: fragment regs -> global, + bias
    const int erow = brow + warp_m * 64 + (lane >> 2);
    const int ecol = bcol + warp_n * 32 + 2 * (lane & 3);
#pragma unroll
    for (int fn = 0; fn < 4; fn++) {
        const int col = ecol + fn * 8;
        const float2 bv = *(const float2*)(bias + col);
#pragma unroll
        for (int fm = 0; fm < 4; fm++) {
            const int r0 = erow + fm * 16;
            float2 o0 = make_float2(c[fm][fn][0] + bv.x, c[fm][fn][1] + bv.y);
            float2 o1 = make_float2(c[fm][fn][2] + bv.x, c[fm][fn][3] + bv.y);
            *(float2*)(C + (size_t)r0 * N + col) = o0;
            *(float2*)(C + (size_t)(r0 + 8) * N + col) = o1;
        }
    }
}

// ---------------- flash attention (unchanged SIMT, fp32) -------------------
__global__ __launch_bounds__(256) void flash_attn_kernel(
    const float* __restrict__ Q, const float* __restrict__ K,
    const float* __restrict__ V, const int* __restrict__ mask,
    float* __restrict__ O, int S)
{
    extern __shared__ float sm[];
    float* Qst = sm;
    float* Kst = Qst + 64 * FPAD;
    float* Vs  = Kst + 64 * FPAD;
    float* Ps  = Vs  + 64 * FPAD;

    const int tid = threadIdx.x;
    const int qt = blockIdx.x, h = blockIdx.y, b = blockIdx.z;
    const int tr = (tid >> 4) * 4;
    const int tc = (tid & 15) * 4;

    const float* Qb = Q + ((long)(b * S + qt * 64)) * H_DIM + h * DHEAD;
    const float* Kb = K + ((long)b * S) * H_DIM + h * DHEAD;
    const float* Vb = V + ((long)b * S) * H_DIM + h * DHEAD;
    const int*   Mb = mask + (long)b * S * S + (long)(qt * 64) * S;

    for (int i = tid; i < 64 * 16; i += 256) {
        int r = i >> 4, c = (i & 15) << 2;
        float4 v = *(const float4*)(Qb + (long)r * H_DIM + c);
        Qst[(c + 0) * FPAD + r] = v.x;
        Qst[(c + 1) * FPAD + r] = v.y;
        Qst[(c + 2) * FPAD + r] = v.z;
        Qst[(c + 3) * FPAD + r] = v.w;
    }

    float m_i[4], l_i[4], acc[4][4];
#pragma unroll
    for (int i = 0; i < 4; i++) {
        m_i[i] = -1e30f;
        l_i[i] = 0.0f;
#pragma unroll
        for (int j = 0; j < 4; j++) acc[i][j] = 0.0f;
    }

    const float scale = 0.125f;
    const int ntiles = S / 64;

    for (int kt = 0; kt < ntiles; kt++) {
        __syncthreads();
        const float* Kp = Kb + (long)(kt * 64) * H_DIM;
        const float* Vp = Vb + (long)(kt * 64) * H_DIM;
        for (int i = tid; i < 64 * 16; i += 256) {
            int r = i >> 4, c = (i & 15) << 2;
            float4 kv = *(const float4*)(Kp + (long)r * H_DIM + c);
            Kst[(c + 0) * FPAD + r] = kv.x;
            Kst[(c + 1) * FPAD + r] = kv.y;
            Kst[(c + 2) * FPAD + r] = kv.z;
            Kst[(c + 3) * FPAD + r] = kv.w;
            float4 vv = *(const float4*)(Vp + (long)r * H_DIM + c);
            *(float4*)&Vs[r * FPAD + c] = vv;
        }
        __syncthreads();

        float s[4][4];
#pragma unroll
        for (int i = 0; i < 4; i++)
#pragma unroll
            for (int j = 0; j < 4; j++) s[i][j] = 0.0f;

#pragma unroll 8
        for (int d = 0; d < 64; d++) {
            float4 a = *(const float4*)&Qst[d * FPAD + tr];
            float4 bb = *(const float4*)&Kst[d * FPAD + tc];
            float av[4] = {a.x, a.y, a.z, a.w};
            float bv[4] = {bb.x, bb.y, bb.z, bb.w};
#pragma unroll
            for (int i = 0; i < 4; i++)
#pragma unroll
                for (int j = 0; j < 4; j++)
                    s[i][j] = fmaf(av[i], bv[j], s[i][j]);
        }

#pragma unroll
        for (int i = 0; i < 4; i++) {
            int4 mm = *(const int4*)&Mb[(long)(tr + i) * S + kt * 64 + tc];
            s[i][0] = (mm.x == 0) ? -10000.0f : s[i][0] * scale;
            s[i][1] = (mm.y == 0) ? -10000.0f : s[i][1] * scale;
            s[i][2] = (mm.z == 0) ? -10000.0f : s[i][2] * scale;
            s[i][3] = (mm.w == 0) ? -10000.0f : s[i][3] * scale;
        }

#pragma unroll
        for (int i = 0; i < 4; i++) {
            float rm = fmaxf(fmaxf(s[i][0], s[i][1]), fmaxf(s[i][2], s[i][3]));
#pragma unroll
            for (int off = 8; off >= 1; off >>= 1)
                rm = fmaxf(rm, __shfl_xor_sync(0xffffffffu, rm, off));
            float mnew = fmaxf(m_i[i], rm);
            float corr = __expf(m_i[i] - mnew);
            float rs = 0.0f;
#pragma unroll
            for (int j = 0; j < 4; j++) {
                float p = __expf(s[i][j] - mnew);
                s[i][j] = p;
                rs += p;
            }
#pragma unroll
            for (int off = 8; off >= 1; off >>= 1)
                rs += __shfl_xor_sync(0xffffffffu, rs, off);
            l_i[i] = l_i[i] * corr + rs;
            m_i[i] = mnew;
#pragma unroll
            for (int j = 0; j < 4; j++) acc[i][j] *= corr;
        }

#pragma unroll
        for (int i = 0; i < 4; i++) {
            float4 p4 = make_float4(s[i][0], s[i][1], s[i][2], s[i][3]);
            *(float4*)&Ps[(tr + i) * FPAD + tc] = p4;
        }
        __syncthreads();

#pragma unroll 8
        for (int k = 0; k < 64; k++) {
            float p0 = Ps[(tr + 0) * FPAD + k];
            float p1 = Ps[(tr + 1) * FPAD + k];
            float p2 = Ps[(tr + 2) * FPAD + k];
            float p3 = Ps[(tr + 3) * FPAD + k];
            float4 vv = *(const float4*)&Vs[k * FPAD + tc];
            float vrow[4] = {vv.x, vv.y, vv.z, vv.w};
            float pr[4] = {p0, p1, p2, p3};
#pragma unroll
            for (int i = 0; i < 4; i++)
#pragma unroll
                for (int j = 0; j < 4; j++)
                    acc[i][j] = fmaf(pr[i], vrow[j], acc[i][j]);
        }
    }

    float* Ob = O + ((long)(b * S + qt * 64)) * H_DIM + h * DHEAD;
#pragma unroll
    for (int i = 0; i < 4; i++) {
        float inv = 1.0f / l_i[i];
        float4 o = make_float4(acc[i][0] * inv, acc[i][1] * inv,
                               acc[i][2] * inv, acc[i][3] * inv);
        *(float4*)&Ob[(long)(tr + i) * H_DIM + tc] = o;
    }
}

// ---------------- launch ---------------------------------------------------
extern "C" void kernel_launch(void* const* d_in, const int* in_sizes, int n_in,
                              void* d_out, int out_size)
{
    const float* q   = (const float*)d_in[0];
    const float* k   = (const float*)d_in[1];
    const float* v   = (const float*)d_in[2];
    const int*   msk = (const int*)d_in[3];
    const float* w_q = (const float*)d_in[4];
    const float* b_q = (const float*)d_in[5];
    const float* w_k = (const float*)d_in[6];
    const float* b_k = (const float*)d_in[7];
    const float* w_v = (const float*)d_in[8];
    const float* b_v = (const float*)d_in[9];
    const float* w_o = (const float*)d_in[10];
    const float* b_o = (const float*)d_in[11];
    float* out = (float*)d_out;

    const int BS = in_sizes[0] / H_DIM;   // B*S = 4096
    const int S  = in_sizes[3] / BS;
    const int B  = BS / S;
    const int M  = BS;
    const int n_elem = M * H_DIM;

    float *gq, *gk, *gv, *ga;
    __nv_bfloat16 *ah, *al, *wh, *wl;
    cudaGetSymbolAddress((void**)&gq, g_q);
    cudaGetSymbolAddress((void**)&gk, g_k);
    cudaGetSymbolAddress((void**)&gv, g_v);
    cudaGetSymbolAddress((void**)&ga, g_a);
    cudaGetSymbolAddress((void**)&ah, g_ah);
    cudaGetSymbolAddress((void**)&al, g_al);
    cudaGetSymbolAddress((void**)&wh, g_wh);
    cudaGetSymbolAddress((void**)&wl, g_wl);

    cudaFuncSetAttribute(hmma_gemm_kernel,
                         cudaFuncAttributeMaxDynamicSharedMemorySize, GEMM_SMEM);

    const dim3 gw(H_DIM / 32, H_DIM / 32);
    const dim3 bw(32, 8);
    const int  ga_grid = n_elem / 4 / 256;
    const dim3 gg(H_DIM / 128, M / 128);

    // Q projection
    wconv_kernel<<<gw, bw>>>(w_q, wh, wl);
    aconv_kernel<<<ga_grid, 256>>>(q, ah, al, n_elem);
    hmma_gemm_kernel<<<gg, 256, GEMM_SMEM>>>(ah, al, wh, wl, b_q, gq, H_DIM);
    // K projection
    wconv_kernel<<<gw, bw>>>(w_k, wh, wl);
    aconv_kernel<<<ga_grid, 256>>>(k, ah, al, n_elem);
    hmma_gemm_kernel<<<gg, 256, GEMM_SMEM>>>(ah, al, wh, wl, b_k, gk, H_DIM);
    // V projection
    wconv_kernel<<<gw, bw>>>(w_v, wh, wl);
    aconv_kernel<<<ga_grid, 256>>>(v, ah, al, n_elem);
    hmma_gemm_kernel<<<gg, 256, GEMM_SMEM>>>(ah, al, wh, wl, b_v, gv, H_DIM);

    // attention
    const size_t SMEM_ATT = (size_t)4 * 64 * FPAD * sizeof(float);
    cudaFuncSetAttribute(flash_attn_kernel,
                         cudaFuncAttributeMaxDynamicSharedMemorySize, (int)SMEM_ATT);
    flash_attn_kernel<<<dim3(S / 64, NHEAD, B), 256, SMEM_ATT>>>(gq, gk, gv, msk, ga, S);

    // O projection
    wconv_kernel<<<gw, bw>>>(w_o, wh, wl);
    aconv_kernel<<<ga_grid, 256>>>(ga, ah, al, n_elem);
    hmma_gemm_kernel<<<gg, 256, GEMM_SMEM>>>(ah, al, wh, wl, b_o, out, H_DIM);
}

// round 4
// speedup vs baseline: 2.3746x; 1.7228x over previous
#include <cuda_runtime.h>
#include <cuda_bf16.h>
#include <cstdint>

#define H_DIM 1024
#define NHEAD 16
#define DHEAD 64

// ---------------- scratch (__device__ globals; no allocs allowed) ----------
__device__ __nv_bfloat16 g_xh[4096 * 1024];
__device__ __nv_bfloat16 g_xl[4096 * 1024];
__device__ __nv_bfloat16 g_qh[4096 * 1024];
__device__ __nv_bfloat16 g_ql[4096 * 1024];
__device__ __nv_bfloat16 g_kh[4096 * 1024];
__device__ __nv_bfloat16 g_kl[4096 * 1024];
__device__ __nv_bfloat16 g_vh[4096 * 1024];
__device__ __nv_bfloat16 g_vl[4096 * 1024];
__device__ __nv_bfloat16 g_oh[4096 * 1024];
__device__ __nv_bfloat16 g_ol[4096 * 1024];
__device__ __nv_bfloat16 g_wh[1024 * 1024];
__device__ __nv_bfloat16 g_wl[1024 * 1024];

// ---------------- helpers --------------------------------------------------
__device__ __forceinline__ uint32_t smem_u32(const void* p) {
    uint32_t a;
    asm("{ .reg .u64 t; cvta.to.shared.u64 t, %1; cvt.u32.u64 %0, t; }" : "=r"(a) : "l"(p));
    return a;
}
__device__ __forceinline__ uint32_t swz(uint32_t off) {
    return off ^ ((off >> 3) & 0x70);
}
__device__ __forceinline__ void cp_async16(uint32_t saddr, const void* g) {
    asm volatile("cp.async.cg.shared.global [%0], [%1], 16;" :: "r"(saddr), "l"(g));
}
__device__ __forceinline__ void cp_commit() {
    asm volatile("cp.async.commit_group;" ::: "memory");
}
template <int N>
__device__ __forceinline__ void cp_wait() {
    asm volatile("cp.async.wait_group %0;" :: "n"(N) : "memory");
}
__device__ __forceinline__ void ldsm4(uint32_t* r, uint32_t addr) {
    asm volatile("ldmatrix.sync.aligned.m8n8.x4.shared.b16 {%0,%1,%2,%3}, [%4];"
                 : "=r"(r[0]), "=r"(r[1]), "=r"(r[2]), "=r"(r[3]) : "r"(addr));
}
__device__ __forceinline__ void ldsm4t(uint32_t* r, uint32_t addr) {
    asm volatile("ldmatrix.sync.aligned.m8n8.x4.trans.shared.b16 {%0,%1,%2,%3}, [%4];"
                 : "=r"(r[0]), "=r"(r[1]), "=r"(r[2]), "=r"(r[3]) : "r"(addr));
}
__device__ __forceinline__ uint32_t lds32(uint32_t addr) {
    uint32_t v;
    asm volatile("ld.shared.b32 %0, [%1];" : "=r"(v) : "r"(addr));
    return v;
}
__device__ __forceinline__ void mma16816(float* c, const uint32_t* a, const uint32_t* b) {
    asm volatile(
        "mma.sync.aligned.m16n8k16.row.col.f32.bf16.bf16.f32 "
        "{%0,%1,%2,%3}, {%4,%5,%6,%7}, {%8,%9}, {%0,%1,%2,%3};"
        : "+f"(c[0]), "+f"(c[1]), "+f"(c[2]), "+f"(c[3])
        : "r"(a[0]), "r"(a[1]), "r"(a[2]), "r"(a[3]), "r"(b[0]), "r"(b[1]));
}
// split two fp32 into packed bf16x2 hi / lo correction
__device__ __forceinline__ void splitpack(float x, float y, uint32_t& hi, uint32_t& lo) {
    __nv_bfloat16 xh = __float2bfloat16(x), yh = __float2bfloat16(y);
    __nv_bfloat16 xl = __float2bfloat16(x - __bfloat162float(xh));
    __nv_bfloat16 yl = __float2bfloat16(y - __bfloat162float(yh));
    __nv_bfloat162 h2(xh, yh), l2(xl, yl);
    hi = *(uint32_t*)&h2;
    lo = *(uint32_t*)&l2;
}

// ---------------- input conversion: fp32 -> bf16 hi/lo ---------------------
__global__ __launch_bounds__(256) void aconv_kernel(
    const float* __restrict__ A, __nv_bfloat16* __restrict__ Ah,
    __nv_bfloat16* __restrict__ Al, int n)
{
    int i = (blockIdx.x * 256 + threadIdx.x) * 4;
    if (i >= n) return;
    float4 v = *(const float4*)(A + i);
    uint32_t h0, l0, h1, l1;
    splitpack(v.x, v.y, h0, l0);
    splitpack(v.z, v.w, h1, l1);
    *(uint32_t*)(Ah + i) = h0;
    *(uint32_t*)(Ah + i + 2) = h1;
    *(uint32_t*)(Al + i) = l0;
    *(uint32_t*)(Al + i + 2) = l1;
}

// transpose W [K,N] -> Wt [N,K] with hi/lo split
__global__ __launch_bounds__(256) void wconv_kernel(
    const float* __restrict__ W, __nv_bfloat16* __restrict__ Wh,
    __nv_bfloat16* __restrict__ Wl)
{
    __shared__ float t[32][33];
    int bx = blockIdx.x * 32, by = blockIdx.y * 32;
    int tx = threadIdx.x, ty = threadIdx.y;
#pragma unroll
    for (int j = 0; j < 32; j += 8)
        t[ty + j][tx] = W[(size_t)(by + ty + j) * H_DIM + bx + tx];
    __syncthreads();
#pragma unroll
    for (int j = 0; j < 32; j += 8) {
        float v = t[tx][ty + j];
        __nv_bfloat16 h = __float2bfloat16(v);
        __nv_bfloat16 l = __float2bfloat16(v - __bfloat162float(h));
        size_t o = (size_t)(bx + ty + j) * H_DIM + by + tx;
        Wh[o] = h;
        Wl[o] = l;
    }
}

// ---------------- HMMA GEMM: C = A @ Wt^T + bias ---------------------------
// Epilogue: fp32 to Cf if non-null, else bf16 hi/lo split to (Ch, Cl).
#define GK 1024
#define TILE16K 16384
#define STAGEB  (4 * TILE16K)
#define NSTG 16
#define GEMM_SMEM (2 * STAGEB)

__global__ __launch_bounds__(256) void hmma_gemm_kernel(
    const __nv_bfloat16* __restrict__ Ah, const __nv_bfloat16* __restrict__ Al,
    const __nv_bfloat16* __restrict__ Bh, const __nv_bfloat16* __restrict__ Bl,
    const float* __restrict__ bias, float* __restrict__ Cf,
    __nv_bfloat16* __restrict__ Ch, __nv_bfloat16* __restrict__ Cl, int N)
{
    extern __shared__ char smem[];
    const uint32_t sb = smem_u32(smem);
    const int tid = threadIdx.x;
    const int wid = tid >> 5, lane = tid & 31;
    const int warp_m = wid & 1, warp_n = wid >> 1;
    const int brow = blockIdx.y * 128, bcol = blockIdx.x * 128;

    const __nv_bfloat16* srcs[4] = {
        Ah + (size_t)brow * GK, Al + (size_t)brow * GK,
        Bh + (size_t)bcol * GK, Bl + (size_t)bcol * GK };

    const int frow[4] = { (tid + 0) >> 3, (tid + 256) >> 3,
                          (tid + 512) >> 3, (tid + 768) >> 3 };
    const int fchk[4] = { (tid + 0) & 7, (tid + 256) & 7,
                          (tid + 512) & 7, (tid + 768) & 7 };

    auto fill = [&](int buf, int k0) {
        const uint32_t stb = sb + buf * STAGEB;
#pragma unroll
        for (int t = 0; t < 4; t++) {
            const __nv_bfloat16* p = srcs[t] + k0;
#pragma unroll
            for (int i = 0; i < 4; i++) {
                const __nv_bfloat16* g = p + (size_t)frow[i] * GK + fchk[i] * 8;
                cp_async16(stb + t * TILE16K + swz(frow[i] * 128 + fchk[i] * 16), g);
            }
        }
        cp_commit();
    };

    float c[4][4][4];
#pragma unroll
    for (int i = 0; i < 4; i++)
#pragma unroll
        for (int j = 0; j < 4; j++)
#pragma unroll
            for (int e = 0; e < 4; e++) c[i][j][e] = 0.0f;

    const int a_row = warp_m * 64 + (lane & 15);
    const int a_chk = lane >> 4;
    const int b_n  = warp_n * 32 + (lane >> 2);
    const int b_kb = 4 * (lane & 3);

    fill(0, 0);

    for (int s = 0; s < NSTG; s++) {
        if (s + 1 < NSTG) fill((s + 1) & 1, (s + 1) * 64);
        if (s + 1 < NSTG) cp_wait<1>(); else cp_wait<0>();
        __syncthreads();

        const uint32_t stb = sb + (s & 1) * STAGEB;
        const uint32_t ah_b = stb, al_b = stb + TILE16K;
        const uint32_t bh_b = stb + 2 * TILE16K, bl_b = stb + 3 * TILE16K;

#pragma unroll
        for (int k16 = 0; k16 < 4; k16++) {
            uint32_t ah[4][4], al[4][4], bh[4][2], bl[4][2];
#pragma unroll
            for (int fm = 0; fm < 4; fm++) {
                uint32_t off = swz((uint32_t)((a_row + fm * 16) * 128 + (a_chk + 2 * k16) * 16));
                ldsm4(ah[fm], ah_b + off);
                ldsm4(al[fm], al_b + off);
            }
#pragma unroll
            for (int fn = 0; fn < 4; fn++) {
                uint32_t o0 = (uint32_t)((b_n + fn * 8) * 128 + k16 * 32 + b_kb);
                uint32_t s0 = swz(o0), s1 = swz(o0 + 16);
                bh[fn][0] = lds32(bh_b + s0);
                bh[fn][1] = lds32(bh_b + s1);
                bl[fn][0] = lds32(bl_b + s0);
                bl[fn][1] = lds32(bl_b + s1);
            }
#pragma unroll
            for (int fm = 0; fm < 4; fm++)
#pragma unroll
                for (int fn = 0; fn < 4; fn++) {
                    mma16816(c[fm][fn], ah[fm], bh[fn]);
                    mma16816(c[fm][fn], al[fm], bh[fn]);
                    mma16816(c[fm][fn], ah[fm], bl[fn]);
                }
        }
        __syncthreads();
    }

    const int erow = brow + warp_m * 64 + (lane >> 2);
    const int ecol = bcol + warp_n * 32 + 2 * (lane & 3);
#pragma unroll
    for (int fn = 0; fn < 4; fn++) {
        const int col = ecol + fn * 8;
        const float2 bv = *(const float2*)(bias + col);
#pragma unroll
        for (int fm = 0; fm < 4; fm++) {
            const int r0 = erow + fm * 16;
            float v00 = c[fm][fn][0] + bv.x, v01 = c[fm][fn][1] + bv.y;
            float v10 = c[fm][fn][2] + bv.x, v11 = c[fm][fn][3] + bv.y;
            if (Cf) {
                *(float2*)(Cf + (size_t)r0 * N + col) = make_float2(v00, v01);
                *(float2*)(Cf + (size_t)(r0 + 8) * N + col) = make_float2(v10, v11);
            } else {
                uint32_t h0, l0, h1, l1;
                splitpack(v00, v01, h0, l0);
                splitpack(v10, v11, h1, l1);
                *(uint32_t*)(Ch + (size_t)r0 * N + col) = h0;
                *(uint32_t*)(Cl + (size_t)r0 * N + col) = l0;
                *(uint32_t*)(Ch + (size_t)(r0 + 8) * N + col) = h1;
                *(uint32_t*)(Cl + (size_t)(r0 + 8) * N + col) = l1;
            }
        }
    }
}

// ---------------- HMMA flash attention -------------------------------------
// CTA = 128 Q rows of one (b,h). 8 warps x 16 q-rows. K/V chunks of 64 keys,
// cp.async double buffer. QK^T and PV both 3-term bf16 split, fp32 softmax.
#define ATT_STAGE 32768          /* Kh Kl Vh Vl tiles (8KB each) */
#define ATT_Q     65536
#define ATT_SMEM  98304

__global__ __launch_bounds__(256) void hmma_attn_kernel(
    const __nv_bfloat16* __restrict__ Qh, const __nv_bfloat16* __restrict__ Ql,
    const __nv_bfloat16* __restrict__ Kh, const __nv_bfloat16* __restrict__ Kl,
    const __nv_bfloat16* __restrict__ Vh, const __nv_bfloat16* __restrict__ Vl,
    const int* __restrict__ mask,
    __nv_bfloat16* __restrict__ Oh, __nv_bfloat16* __restrict__ Ol, int S)
{
    extern __shared__ char smem[];
    const uint32_t sb = smem_u32(smem);
    const int tid = threadIdx.x, wid = tid >> 5, lane = tid & 31;
    const int qt = blockIdx.x, h = blockIdx.y, b = blockIdx.z;

    const size_t bh = (size_t)b * S * H_DIM + h * DHEAD;
    const __nv_bfloat16* srcs[4] = { Kh + bh, Kl + bh, Vh + bh, Vl + bh };

    // Q tile (hi/lo) -> smem, once
    {
        const size_t qoff = bh + (size_t)qt * 128 * H_DIM;
#pragma unroll
        for (int i = 0; i < 8; i++) {
            int idx = tid + i * 256;
            int t = idx >> 10, row = (idx >> 3) & 127, chk = idx & 7;
            const __nv_bfloat16* g = (t ? Ql : Qh) + qoff + (size_t)row * H_DIM + chk * 8;
            cp_async16(sb + ATT_Q + t * 16384 + swz(row * 128 + chk * 16), g);
        }
    }
    cp_commit();

    auto fillkv = [&](int buf, int kt) {
        const uint32_t stb = sb + buf * ATT_STAGE;
#pragma unroll
        for (int i = 0; i < 8; i++) {
            int idx = tid + i * 256;
            int t = idx >> 9, row = (idx >> 3) & 63, chk = idx & 7;
            const __nv_bfloat16* g = srcs[t] + (size_t)(kt * 64 + row) * H_DIM + chk * 8;
            cp_async16(stb + t * 8192 + swz(row * 128 + chk * 16), g);
        }
        cp_commit();
    };

    fillkv(0, 0);
    cp_wait<0>();
    __syncthreads();

    // Q fragments to registers (A-operand, m16k16 x 4 k-steps, hi/lo)
    uint32_t qfh[4][4], qfl[4][4];
    {
        const int row = wid * 16 + (lane & 15);
#pragma unroll
        for (int j = 0; j < 4; j++) {
            uint32_t off = swz((uint32_t)(row * 128 + (2 * j + (lane >> 4)) * 16));
            ldsm4(qfh[j], sb + ATT_Q + off);
            ldsm4(qfl[j], sb + ATT_Q + 16384 + off);
        }
    }

    float o[8][4];
#pragma unroll
    for (int i = 0; i < 8; i++)
#pragma unroll
        for (int e = 0; e < 4; e++) o[i][e] = 0.0f;
    float m0 = -1e30f, m1 = -1e30f, l0 = 0.0f, l1 = 0.0f;

    const int grow = qt * 128 + wid * 16 + (lane >> 2);
    const int* mbase = mask + (size_t)b * S * S + (size_t)grow * S + 2 * (lane & 3);

    const int nch = S / 64;
    for (int c = 0; c < nch; c++) {
        if (c + 1 < nch) fillkv((c + 1) & 1, c + 1);
        if (c + 1 < nch) cp_wait<1>(); else cp_wait<0>();
        __syncthreads();
        const uint32_t st = sb + (c & 1) * ATT_STAGE;

        // ---- scores: s = Q @ K^T (3-term split) ----
        float s[8][4];
#pragma unroll
        for (int nt = 0; nt < 8; nt++)
#pragma unroll
            for (int e = 0; e < 4; e++) s[nt][e] = 0.0f;

#pragma unroll
        for (int j = 0; j < 4; j++) {
#pragma unroll
            for (int nt = 0; nt < 8; nt++) {
                uint32_t ro = (uint32_t)((nt * 8 + (lane >> 2)) * 128 + j * 32 + 4 * (lane & 3));
                uint32_t s0 = swz(ro), s1 = swz(ro + 16);
                uint32_t kb[2]  = { lds32(st + s0), lds32(st + s1) };
                uint32_t kbl[2] = { lds32(st + 8192 + s0), lds32(st + 8192 + s1) };
                mma16816(s[nt], qfh[j], kb);
                mma16816(s[nt], qfl[j], kb);
                mma16816(s[nt], qfh[j], kbl);
            }
        }

        // ---- mask + scale ----
        const int* mr = mbase + c * 64;
#pragma unroll
        for (int nt = 0; nt < 8; nt++) {
            int2 ma = *(const int2*)(mr + nt * 8);
            int2 mb2 = *(const int2*)(mr + 8 * S + nt * 8);
            s[nt][0] = (ma.x == 0) ? -10000.0f : s[nt][0] * 0.125f;
            s[nt][1] = (ma.y == 0) ? -10000.0f : s[nt][1] * 0.125f;
            s[nt][2] = (mb2.x == 0) ? -10000.0f : s[nt][2] * 0.125f;
            s[nt][3] = (mb2.y == 0) ? -10000.0f : s[nt][3] * 0.125f;
        }

        // ---- online softmax (rows r=lane>>2 and r+8) ----
        float mx0 = -1e30f, mx1 = -1e30f;
#pragma unroll
        for (int nt = 0; nt < 8; nt++) {
            mx0 = fmaxf(mx0, fmaxf(s[nt][0], s[nt][1]));
            mx1 = fmaxf(mx1, fmaxf(s[nt][2], s[nt][3]));
        }
        mx0 = fmaxf(mx0, __shfl_xor_sync(0xffffffffu, mx0, 1));
        mx0 = fmaxf(mx0, __shfl_xor_sync(0xffffffffu, mx0, 2));
        mx1 = fmaxf(mx1, __shfl_xor_sync(0xffffffffu, mx1, 1));
        mx1 = fmaxf(mx1, __shfl_xor_sync(0xffffffffu, mx1, 2));

        float mn0 = fmaxf(m0, mx0), mn1 = fmaxf(m1, mx1);
        float cr0 = __expf(m0 - mn0), cr1 = __expf(m1 - mn1);
        float rs0 = 0.0f, rs1 = 0.0f;
#pragma unroll
        for (int nt = 0; nt < 8; nt++) {
            s[nt][0] = __expf(s[nt][0] - mn0);
            s[nt][1] = __expf(s[nt][1] - mn0);
            s[nt][2] = __expf(s[nt][2] - mn1);
            s[nt][3] = __expf(s[nt][3] - mn1);
            rs0 += s[nt][0] + s[nt][1];
            rs1 += s[nt][2] + s[nt][3];
        }
        rs0 += __shfl_xor_sync(0xffffffffu, rs0, 1);
        rs0 += __shfl_xor_sync(0xffffffffu, rs0, 2);
        rs1 += __shfl_xor_sync(0xffffffffu, rs1, 1);
        rs1 += __shfl_xor_sync(0xffffffffu, rs1, 2);
        l0 = l0 * cr0 + rs0;
        l1 = l1 * cr1 + rs1;
        m0 = mn0;
        m1 = mn1;
#pragma unroll
        for (int nt = 0; nt < 8; nt++) {
            o[nt][0] *= cr0;
            o[nt][1] *= cr0;
            o[nt][2] *= cr1;
            o[nt][3] *= cr1;
        }

        // ---- O += P @ V (3-term split; P from score regs) ----
#pragma unroll
        for (int j = 0; j < 4; j++) {
            uint32_t pah[4], pal[4];
            splitpack(s[2 * j][0], s[2 * j][1], pah[0], pal[0]);
            splitpack(s[2 * j][2], s[2 * j][3], pah[1], pal[1]);
            splitpack(s[2 * j + 1][0], s[2 * j + 1][1], pah[2], pal[2]);
            splitpack(s[2 * j + 1][2], s[2 * j + 1][3], pah[3], pal[3]);
#pragma unroll
            for (int db = 0; db < 4; db++) {
                uint32_t off = swz((uint32_t)((j * 16 + (lane & 15)) * 128
                                              + (db * 2 + (lane >> 4)) * 16));
                uint32_t vfh[4], vfl[4];
                ldsm4t(vfh, st + 16384 + off);
                ldsm4t(vfl, st + 24576 + off);
                mma16816(o[db * 2], pah, vfh);
                mma16816(o[db * 2], pal, vfh);
                mma16816(o[db * 2], pah, vfl);
                mma16816(o[db * 2 + 1], pah, vfh + 2);
                mma16816(o[db * 2 + 1], pal, vfh + 2);
                mma16816(o[db * 2 + 1], pah, vfl + 2);
            }
        }
        __syncthreads();
    }

    // ---- epilogue: normalize, split hi/lo, store for O-projection ----
    const float i0 = 1.0f / l0, i1 = 1.0f / l1;
    const size_t ob = (size_t)(b * S + grow) * H_DIM + h * DHEAD + 2 * (lane & 3);
#pragma unroll
    for (int nt = 0; nt < 8; nt++) {
        uint32_t h0, lo0, h1, lo1;
        splitpack(o[nt][0] * i0, o[nt][1] * i0, h0, lo0);
        splitpack(o[nt][2] * i1, o[nt][3] * i1, h1, lo1);
        *(uint32_t*)(Oh + ob + nt * 8) = h0;
        *(uint32_t*)(Ol + ob + nt * 8) = lo0;
        *(uint32_t*)(Oh + ob + 8 * H_DIM + nt * 8) = h1;
        *(uint32_t*)(Ol + ob + 8 * H_DIM + nt * 8) = lo1;
    }
}

// ---------------- launch ---------------------------------------------------
extern "C" void kernel_launch(void* const* d_in, const int* in_sizes, int n_in,
                              void* d_out, int out_size)
{
    const float* q   = (const float*)d_in[0];
    const float* k   = (const float*)d_in[1];
    const float* v   = (const float*)d_in[2];
    const int*   msk = (const int*)d_in[3];
    const float* w_q = (const float*)d_in[4];
    const float* b_q = (const float*)d_in[5];
    const float* w_k = (const float*)d_in[6];
    const float* b_k = (const float*)d_in[7];
    const float* w_v = (const float*)d_in[8];
    const float* b_v = (const float*)d_in[9];
    const float* w_o = (const float*)d_in[10];
    const float* b_o = (const float*)d_in[11];
    float* out = (float*)d_out;

    const int BS = in_sizes[0] / H_DIM;   // B*S = 4096
    const int S  = in_sizes[3] / BS;
    const int B  = BS / S;
    const int M  = BS;
    const int n_elem = M * H_DIM;

    __nv_bfloat16 *xh, *xl, *qh, *ql, *kh, *kl, *vh, *vl, *oh, *ol, *wh, *wl;
    cudaGetSymbolAddress((void**)&xh, g_xh);
    cudaGetSymbolAddress((void**)&xl, g_xl);
    cudaGetSymbolAddress((void**)&qh, g_qh);
    cudaGetSymbolAddress((void**)&ql, g_ql);
    cudaGetSymbolAddress((void**)&kh, g_kh);
    cudaGetSymbolAddress((void**)&kl, g_kl);
    cudaGetSymbolAddress((void**)&vh, g_vh);
    cudaGetSymbolAddress((void**)&vl, g_vl);
    cudaGetSymbolAddress((void**)&oh, g_oh);
    cudaGetSymbolAddress((void**)&ol, g_ol);
    cudaGetSymbolAddress((void**)&wh, g_wh);
    cudaGetSymbolAddress((void**)&wl, g_wl);

    cudaFuncSetAttribute(hmma_gemm_kernel,
                         cudaFuncAttributeMaxDynamicSharedMemorySize, GEMM_SMEM);
    cudaFuncSetAttribute(hmma_attn_kernel,
                         cudaFuncAttributeMaxDynamicSharedMemorySize, ATT_SMEM);

    const dim3 gw(H_DIM / 32, H_DIM / 32);
    const dim3 bw(32, 8);
    const int  ga_grid = n_elem / 4 / 256;
    const dim3 gg(H_DIM / 128, M / 128);

    // Q projection -> bf16 hi/lo
    wconv_kernel<<<gw, bw>>>(w_q, wh, wl);
    aconv_kernel<<<ga_grid, 256>>>(q, xh, xl, n_elem);
    hmma_gemm_kernel<<<gg, 256, GEMM_SMEM>>>(xh, xl, wh, wl, b_q, nullptr, qh, ql, H_DIM);
    // K projection
    wconv_kernel<<<gw, bw>>>(w_k, wh, wl);
    aconv_kernel<<<ga_grid, 256>>>(k, xh, xl, n_elem);
    hmma_gemm_kernel<<<gg, 256, GEMM_SMEM>>>(xh, xl, wh, wl, b_k, nullptr, kh, kl, H_DIM);
    // V projection
    wconv_kernel<<<gw, bw>>>(w_v, wh, wl);
    aconv_kernel<<<ga_grid, 256>>>(v, xh, xl, n_elem);
    hmma_gemm_kernel<<<gg, 256, GEMM_SMEM>>>(xh, xl, wh, wl, b_v, nullptr, vh, vl, H_DIM);

    // attention (tensor cores, 3-term split)
    hmma_attn_kernel<<<dim3(S / 128, NHEAD, B), 256, ATT_SMEM>>>(
        qh, ql, kh, kl, vh, vl, msk, oh, ol, S);

    // O projection -> fp32 out
    wconv_kernel<<<gw, bw>>>(w_o, wh, wl);
    hmma_gemm_kernel<<<gg, 256, GEMM_SMEM>>>(oh, ol, wh, wl, b_o, out, nullptr, nullptr, H_DIM);
}